// round 1
// baseline (speedup 1.0000x reference)
#include <cuda_runtime.h>
#include <math.h>

// Problem constants (fixed shapes)
#define Dm  512
#define Tm  2048
#define Bm  2
#define Hm  8
#define HDm 64
#define Mtot (Bm * Tm)   // 4096

// Scratch (allocation-free rule: __device__ globals)
__device__ float g_Q[Bm * Hm * Tm * HDm];   // (B,H,T,hd)
__device__ float g_K[Bm * Hm * Tm * HDm];
__device__ float g_V[Bm * Hm * Tm * HDm];
__device__ float g_att[Bm * Tm * Dm];       // (B,T,D)

// ---------------------------------------------------------------------------
// GEMM core: C(MxN) = A(MxK) @ W(NxK)^T   (both A and W are K-contiguous)
// Tile 128x128x8, 256 threads, 8x8 microtile per thread. M=4096,N=512,K=512.
// ---------------------------------------------------------------------------
__device__ __forceinline__ void gemm_tile(
    const float* __restrict__ A, const float* __restrict__ W,
    float (&acc)[8][8], float (*As)[128], float (*Ws)[128])
{
    const int m0 = blockIdx.y * 128;
    const int n0 = blockIdx.x * 128;
    const int t  = threadIdx.x;
    const int lrow = t >> 1;           // 0..127
    const int lseg = (t & 1) * 4;      // 0 or 4
    const int tx = t & 15;
    const int ty = t >> 4;

    for (int k0 = 0; k0 < Dm; k0 += 8) {
        // prefetch global into regs
        float4 av = *(const float4*)(A + (size_t)(m0 + lrow) * Dm + k0 + lseg);
        float4 wv = *(const float4*)(W + (size_t)(n0 + lrow) * Dm + k0 + lseg);
        __syncthreads();   // previous iter's compute done before overwrite
        As[lseg + 0][lrow] = av.x; As[lseg + 1][lrow] = av.y;
        As[lseg + 2][lrow] = av.z; As[lseg + 3][lrow] = av.w;
        Ws[lseg + 0][lrow] = wv.x; Ws[lseg + 1][lrow] = wv.y;
        Ws[lseg + 2][lrow] = wv.z; Ws[lseg + 3][lrow] = wv.w;
        __syncthreads();
#pragma unroll
        for (int kk = 0; kk < 8; kk++) {
            float a[8], b[8];
            *(float4*)(a)     = *(const float4*)(&As[kk][ty * 8]);
            *(float4*)(a + 4) = *(const float4*)(&As[kk][ty * 8 + 4]);
            *(float4*)(b)     = *(const float4*)(&Ws[kk][tx * 8]);
            *(float4*)(b + 4) = *(const float4*)(&Ws[kk][tx * 8 + 4]);
#pragma unroll
            for (int i = 0; i < 8; i++)
#pragma unroll
                for (int j = 0; j < 8; j++)
                    acc[i][j] = fmaf(a[i], b[j], acc[i][j]);
        }
    }
}

// ---------------------------------------------------------------------------
// Fused QKV projection: z in {0,1,2} selects (Wq,bq)->g_Q etc.
// Epilogue writes in (B,H,T,hd) layout.
// ---------------------------------------------------------------------------
__global__ void __launch_bounds__(256, 2) qkv_kernel(
    const float* __restrict__ x,
    const float* __restrict__ Wq, const float* __restrict__ bq,
    const float* __restrict__ Wk, const float* __restrict__ bk,
    const float* __restrict__ Wv, const float* __restrict__ bv)
{
    __shared__ float As[8][128];
    __shared__ float Ws[8][128];
    const float* W; const float* bias; float* out;
    if (blockIdx.z == 0)      { W = Wq; bias = bq; out = g_Q; }
    else if (blockIdx.z == 1) { W = Wk; bias = bk; out = g_K; }
    else                      { W = Wv; bias = bv; out = g_V; }

    float acc[8][8] = {};
    gemm_tile(x, W, acc, As, Ws);

    const int m0 = blockIdx.y * 128, n0 = blockIdx.x * 128;
    const int tx = threadIdx.x & 15, ty = threadIdx.x >> 4;
#pragma unroll
    for (int i = 0; i < 8; i++) {
        int m  = m0 + ty * 8 + i;
        int bb = m >> 11;        // / Tm
        int tt = m & (Tm - 1);
#pragma unroll
        for (int j = 0; j < 8; j++) {
            int n = n0 + tx * 8 + j;
            int h = n >> 6, d = n & 63;
            out[(((size_t)(bb * Hm + h) * Tm + tt) << 6) + d] = acc[i][j] + bias[n];
        }
    }
}

// ---------------------------------------------------------------------------
// Local-window attention: one warp per (b,h,query). Window [i-16, i+16) clipped.
// ---------------------------------------------------------------------------
__global__ void __launch_bounds__(256) attn_kernel()
{
    const int warp = (blockIdx.x << 3) + (threadIdx.x >> 5);  // 0..32767
    const int lane = threadIdx.x & 31;
    const int i  = warp & (Tm - 1);
    const int bh = warp >> 11;                 // 0..15
    const int s  = max(0, i - 16);
    const int e  = min(Tm, i + 16);
    const int cnt = e - s;                     // 16..32
    const float scale = 0.125f;                // 1/sqrt(64)

    const float4* qrow = (const float4*)(g_Q + ((size_t)(bh * Tm + i) << 6));
    float score = -INFINITY;
    if (lane < cnt) {
        const float4* krow = (const float4*)(g_K + ((size_t)(bh * Tm + s + lane) << 6));
        float sdot = 0.f;
#pragma unroll
        for (int d4 = 0; d4 < 16; d4++) {
            float4 q = qrow[d4], k = krow[d4];
            sdot += q.x * k.x + q.y * k.y + q.z * k.z + q.w * k.w;
        }
        score = sdot * scale;
    }
    // warp softmax
    float mmax = score;
#pragma unroll
    for (int off = 16; off; off >>= 1)
        mmax = fmaxf(mmax, __shfl_xor_sync(0xffffffffu, mmax, off));
    float p = __expf(score - mmax);            // exp(-inf) == 0 for masked lanes
    float psum = p;
#pragma unroll
    for (int off = 16; off; off >>= 1)
        psum += __shfl_xor_sync(0xffffffffu, psum, off);
    const float inv = 1.0f / psum;

    // AV: lane owns head-dims {lane, lane+32} -> coalesced V reads
    float acc0 = 0.f, acc1 = 0.f;
    const float* vbase = g_V + ((size_t)(bh * Tm + s) << 6);
    for (int j = 0; j < cnt; j++) {
        float pj = __shfl_sync(0xffffffffu, p, j);
        acc0 = fmaf(pj, vbase[(j << 6) + lane], acc0);
        acc1 = fmaf(pj, vbase[(j << 6) + lane + 32], acc1);
    }
    const int b = bh >> 3, h = bh & 7;
    float* orow = g_att + (size_t)(b * Tm + i) * Dm + (h << 6);
    orow[lane]      = acc0 * inv;
    orow[lane + 32] = acc1 * inv;
}

// ---------------------------------------------------------------------------
// Output projection: out = g_att @ Wo^T + bo, plain (B*T, D) row-major.
// ---------------------------------------------------------------------------
__global__ void __launch_bounds__(256, 2) oproj_kernel(
    const float* __restrict__ Wo, const float* __restrict__ bo,
    float* __restrict__ out)
{
    __shared__ float As[8][128];
    __shared__ float Ws[8][128];
    float acc[8][8] = {};
    gemm_tile(g_att, Wo, acc, As, Ws);

    const int m0 = blockIdx.y * 128, n0 = blockIdx.x * 128;
    const int tx = threadIdx.x & 15, ty = threadIdx.x >> 4;
#pragma unroll
    for (int i = 0; i < 8; i++) {
        int m = m0 + ty * 8 + i;
#pragma unroll
        for (int j = 0; j < 8; j++) {
            int n = n0 + tx * 8 + j;
            out[(size_t)m * Dm + n] = acc[i][j] + bo[n];
        }
    }
}

// ---------------------------------------------------------------------------
extern "C" void kernel_launch(void* const* d_in, const int* in_sizes, int n_in,
                              void* d_out, int out_size)
{
    const float* x  = (const float*)d_in[0];
    const float* Wq = (const float*)d_in[1];
    const float* bq = (const float*)d_in[2];
    const float* Wk = (const float*)d_in[3];
    const float* bk = (const float*)d_in[4];
    const float* Wv = (const float*)d_in[5];
    const float* bv = (const float*)d_in[6];
    const float* Wo = (const float*)d_in[7];
    const float* bo = (const float*)d_in[8];
    float* out = (float*)d_out;

    dim3 gqkv(Dm / 128, Mtot / 128, 3);        // 4 x 32 x 3 = 384 CTAs
    qkv_kernel<<<gqkv, 256>>>(x, Wq, bq, Wk, bk, Wv, bv);

    attn_kernel<<<(Bm * Hm * Tm) / 8, 256>>>();   // 4096 CTAs, warp/query

    dim3 go(Dm / 128, Mtot / 128);             // 4 x 32 = 128 CTAs
    oproj_kernel<<<go, 256>>>(Wo, bo, out);
}

// round 3
// speedup vs baseline: 3.0095x; 3.0095x over previous
#include <cuda_runtime.h>
#include <cuda_bf16.h>
#include <cstdint>
#include <math.h>

#define Dm 512
#define Tm 2048
#define Bm 2
#define Hm 8
#define Mtot 4096          // B*T
#define KC 64              // K-chunk
#define NSTEP 8            // 512/64

// ---------------- scratch (__device__ globals) ------------------------------
__device__ float g_Q[Bm*Hm*Tm*64];   // (B,H,T,hd)
__device__ float g_K[Bm*Hm*Tm*64];
__device__ float g_V[Bm*Hm*Tm*64];
__device__ float g_att[Mtot*Dm];     // (B,T,D)

// ---------------- helpers ---------------------------------------------------
__device__ __forceinline__ uint32_t s2u(const void* p) {
    uint32_t a;
    asm("{\n\t.reg .u64 t;\n\tcvta.to.shared.u64 t, %1;\n\tcvt.u32.u64 %0, t;\n\t}"
        : "=r"(a) : "l"(p));
    return a;
}
#define SWZ(o) ((o) ^ (((o) >> 3) & 0x70))

__device__ __forceinline__ void ldsm4(uint32_t (&r)[4], uint32_t addr) {
    asm volatile("ldmatrix.sync.aligned.m8n8.x4.shared.b16 {%0,%1,%2,%3}, [%4];"
                 : "=r"(r[0]), "=r"(r[1]), "=r"(r[2]), "=r"(r[3]) : "r"(addr));
}

__device__ __forceinline__ void mma_bf16(float (&c)[4], const uint32_t (&a)[4],
                                         uint32_t b0, uint32_t b1) {
    asm volatile(
        "mma.sync.aligned.m16n8k16.row.col.f32.bf16.bf16.f32 "
        "{%0,%1,%2,%3}, {%4,%5,%6,%7}, {%8,%9}, {%0,%1,%2,%3};"
        : "+f"(c[0]), "+f"(c[1]), "+f"(c[2]), "+f"(c[3])
        : "r"(a[0]), "r"(a[1]), "r"(a[2]), "r"(a[3]), "r"(b0), "r"(b1));
}

// fp32x4 -> bf16 hi/lo packed pairs
__device__ __forceinline__ void split4(float4 v, uint2& hi, uint2& lo) {
    __nv_bfloat16 h0 = __float2bfloat16(v.x), h1 = __float2bfloat16(v.y);
    __nv_bfloat16 h2 = __float2bfloat16(v.z), h3 = __float2bfloat16(v.w);
    __nv_bfloat16 l0 = __float2bfloat16(v.x - __bfloat162float(h0));
    __nv_bfloat16 l1 = __float2bfloat16(v.y - __bfloat162float(h1));
    __nv_bfloat16 l2 = __float2bfloat16(v.z - __bfloat162float(h2));
    __nv_bfloat16 l3 = __float2bfloat16(v.w - __bfloat162float(h3));
    hi.x = (uint32_t)__bfloat16_as_ushort(h0) | ((uint32_t)__bfloat16_as_ushort(h1) << 16);
    hi.y = (uint32_t)__bfloat16_as_ushort(h2) | ((uint32_t)__bfloat16_as_ushort(h3) << 16);
    lo.x = (uint32_t)__bfloat16_as_ushort(l0) | ((uint32_t)__bfloat16_as_ushort(l1) << 16);
    lo.y = (uint32_t)__bfloat16_as_ushort(l2) | ((uint32_t)__bfloat16_as_ushort(l3) << 16);
}

// ---------------- GEMM core: C(128x128) = A(fp32, MxK) @ W(fp32, NxK)^T -----
// 512 threads, 16 warps (2 m x 8 n), warp tile 64x16, bf16 split x3 via HMMA.
// dyn smem: 2 stages x 64KB; stage = {Ahi,Alo,Whi,Wlo} each 128x64 bf16 (16KB).
__device__ __forceinline__ void gemm_core(
    const float* __restrict__ A, const float* __restrict__ W,
    float (&acc)[4][2][4], char* sm)
{
    const int tid  = threadIdx.x;
    const int wid  = tid >> 5, lane = tid & 31;
    const int wm   = wid >> 3, wn = wid & 7;
    const int m0   = blockIdx.y * 128, n0 = blockIdx.x * 128;
    const uint32_t sb = s2u(sm);

    const int lr = tid >> 4;            // load row (0..31 per it-group)
    const int lc4 = (tid & 15) * 4;     // load col (fp32 elems)

    float4 sA[4], sW[4];

    // fragment addressing
    const int arow = wm * 64 + (lane & 15);
    const int ak8  = (lane >> 4);                       // k-half selector
    const int brow = wn * 16 + ((lane >> 4) << 3) + (lane & 7);
    const int bk8  = (lane >> 3) & 1;

    // prefetch chunk 0
    {
        const float* Ap = A + (size_t)m0 * Dm;
        const float* Wp = W + (size_t)n0 * Dm;
#pragma unroll
        for (int it = 0; it < 4; it++) {
            int r = lr + it * 32;
            sA[it] = *(const float4*)(Ap + (size_t)r * Dm + lc4);
            sW[it] = *(const float4*)(Wp + (size_t)r * Dm + lc4);
        }
    }

#pragma unroll
    for (int c = 0; c < NSTEP; c++) {
        const int buf = c & 1;
        char* tb = sm + buf * 65536;
        if (c > 0) __syncthreads();
        // convert + store staged chunk
#pragma unroll
        for (int it = 0; it < 4; it++) {
            int r = lr + it * 32;
            uint32_t sw = SWZ(r * 128 + lc4 * 2);
            uint2 hi, lo;
            split4(sA[it], hi, lo);
            *(uint2*)(tb + sw)         = hi;
            *(uint2*)(tb + 16384 + sw) = lo;
            split4(sW[it], hi, lo);
            *(uint2*)(tb + 32768 + sw) = hi;
            *(uint2*)(tb + 49152 + sw) = lo;
        }
        __syncthreads();
        // prefetch next chunk (LDGs in flight during MMA)
        if (c < NSTEP - 1) {
            const float* Ap = A + (size_t)m0 * Dm + (c + 1) * KC;
            const float* Wp = W + (size_t)n0 * Dm + (c + 1) * KC;
#pragma unroll
            for (int it = 0; it < 4; it++) {
                int r = lr + it * 32;
                sA[it] = *(const float4*)(Ap + (size_t)r * Dm + lc4);
                sW[it] = *(const float4*)(Wp + (size_t)r * Dm + lc4);
            }
        }
        const uint32_t tbu = sb + buf * 65536;
#pragma unroll
        for (int kt = 0; kt < 4; kt++) {
            uint32_t ah[4][4], al[4][4];
#pragma unroll
            for (int mi = 0; mi < 4; mi++) {
                uint32_t off = (uint32_t)(arow + mi * 16) * 128 + (kt * 16 + ak8 * 8) * 2;
                uint32_t sw = SWZ(off);
                ldsm4(ah[mi], tbu + sw);
                ldsm4(al[mi], tbu + 16384 + sw);
            }
            uint32_t bh[4], bl[4];
            {
                uint32_t off = (uint32_t)brow * 128 + (kt * 16 + bk8 * 8) * 2;
                uint32_t sw = SWZ(off);
                ldsm4(bh, tbu + 32768 + sw);
                ldsm4(bl, tbu + 49152 + sw);
            }
#pragma unroll
            for (int mi = 0; mi < 4; mi++) {
#pragma unroll
                for (int nj = 0; nj < 2; nj++) {
                    mma_bf16(acc[mi][nj], ah[mi], bh[nj * 2], bh[nj * 2 + 1]);
                    mma_bf16(acc[mi][nj], ah[mi], bl[nj * 2], bl[nj * 2 + 1]);
                    mma_bf16(acc[mi][nj], al[mi], bh[nj * 2], bh[nj * 2 + 1]);
                }
            }
        }
    }
}

// ---------------- QKV projection --------------------------------------------
__global__ void __launch_bounds__(512, 1) qkv_mma_kernel(
    const float* __restrict__ x,
    const float* __restrict__ Wq, const float* __restrict__ bq,
    const float* __restrict__ Wk, const float* __restrict__ bk,
    const float* __restrict__ Wv, const float* __restrict__ bv)
{
    extern __shared__ __align__(16) char sm[];
    const int z = blockIdx.z;
    const float* W    = (z == 0) ? Wq : (z == 1) ? Wk : Wv;
    const float* bias = (z == 0) ? bq : (z == 1) ? bk : bv;
    float* out        = (z == 0) ? g_Q : (z == 1) ? g_K : g_V;

    float acc[4][2][4] = {};
    gemm_core(x, W, acc, sm);

    const int wid = threadIdx.x >> 5, lane = threadIdx.x & 31;
    const int wm = wid >> 3, wn = wid & 7;
    const int m0 = blockIdx.y * 128, n0 = blockIdx.x * 128;
    const int b = m0 >> 11, t0 = m0 & (Tm - 1);
#pragma unroll
    for (int mi = 0; mi < 4; mi++) {
#pragma unroll
        for (int nj = 0; nj < 2; nj++) {
            int rowl = wm * 64 + mi * 16 + (lane >> 2);
            int n = n0 + wn * 16 + nj * 8 + (lane & 3) * 2;
            int h = n >> 6, d = n & 63;
            float2 bb = *(const float2*)(bias + n);
            size_t rb = ((size_t)(b * Hm + h) * Tm) << 6;
            float2 v0 = { acc[mi][nj][0] + bb.x, acc[mi][nj][1] + bb.y };
            float2 v1 = { acc[mi][nj][2] + bb.x, acc[mi][nj][3] + bb.y };
            *(float2*)&out[rb + ((size_t)(t0 + rowl) << 6) + d]     = v0;
            *(float2*)&out[rb + ((size_t)(t0 + rowl + 8) << 6) + d] = v1;
        }
    }
}

// ---------------- output projection -----------------------------------------
__global__ void __launch_bounds__(512, 1) oproj_mma_kernel(
    const float* __restrict__ Wo, const float* __restrict__ bo,
    float* __restrict__ out)
{
    extern __shared__ __align__(16) char sm2[];
    float acc[4][2][4] = {};
    gemm_core(g_att, Wo, acc, sm2);

    const int wid = threadIdx.x >> 5, lane = threadIdx.x & 31;
    const int wm = wid >> 3, wn = wid & 7;
    const int m0 = blockIdx.y * 128, n0 = blockIdx.x * 128;
#pragma unroll
    for (int mi = 0; mi < 4; mi++) {
#pragma unroll
        for (int nj = 0; nj < 2; nj++) {
            int rowl = wm * 64 + mi * 16 + (lane >> 2);
            int n = n0 + wn * 16 + nj * 8 + (lane & 3) * 2;
            float2 bb = *(const float2*)(bo + n);
            float2 v0 = { acc[mi][nj][0] + bb.x, acc[mi][nj][1] + bb.y };
            float2 v1 = { acc[mi][nj][2] + bb.x, acc[mi][nj][3] + bb.y };
            *(float2*)&out[(size_t)(m0 + rowl) * Dm + n]       = v0;
            *(float2*)&out[(size_t)(m0 + rowl + 8) * Dm + n]   = v1;
        }
    }
}

// ---------------- local-window attention (smem K/V/Q) ------------------------
__global__ void __launch_bounds__(256, 1) attn_kernel()
{
    extern __shared__ float sf[];   // sK [0,10240), sV [10240,20480), sQ [20480,28672)
    const int tid = threadIdx.x;
    const int bh = blockIdx.y;
    const int q0 = blockIdx.x * 128;
    const int b0 = q0 - 16;
    const size_t base = (size_t)bh * Tm;

    for (int idx = tid; idx < 160 * 16; idx += 256) {
        int r = idx >> 4, d4 = (idx & 15) * 4;
        int row = b0 + r;
        if (row >= 0 && row < Tm) {
            *(float4*)&sf[r * 64 + d4]         = *(const float4*)(g_K + ((base + row) << 6) + d4);
            *(float4*)&sf[10240 + r * 64 + d4] = *(const float4*)(g_V + ((base + row) << 6) + d4);
        }
    }
    for (int idx = tid; idx < 128 * 16; idx += 256) {
        int r = idx >> 4, d4 = (idx & 15) * 4;
        *(float4*)&sf[20480 + r * 64 + d4] = *(const float4*)(g_Q + ((base + q0 + r) << 6) + d4);
    }
    __syncthreads();

    const int wid = tid >> 5, lane = tid & 31;
    for (int qi = 0; qi < 16; qi++) {
        const int iq = q0 + wid * 16 + qi;
        const int s = max(0, iq - 16), e = min(Tm, iq + 16);
        const int cnt = e - s, r0 = s - b0;

        float score = -INFINITY;
        if (lane < cnt) {
            const float* kr = &sf[(r0 + lane) * 64];
            const float* qr = &sf[20480 + (iq - q0) * 64];
            float sum = 0.f;
#pragma unroll
            for (int dd = 0; dd < 64; dd++) {
                int d = (dd + lane) & 63;     // skew: conflict-free
                sum = fmaf(qr[d], kr[d], sum);
            }
            score = sum * 0.125f;
        }
        float mmax = score;
#pragma unroll
        for (int off = 16; off; off >>= 1)
            mmax = fmaxf(mmax, __shfl_xor_sync(0xffffffffu, mmax, off));
        float p = __expf(score - mmax);
        float ps = p;
#pragma unroll
        for (int off = 16; off; off >>= 1)
            ps += __shfl_xor_sync(0xffffffffu, ps, off);
        const float inv = 1.0f / ps;

        float a0 = 0.f, a1 = 0.f;
        const float* vb = &sf[10240 + r0 * 64];
        for (int j = 0; j < cnt; j++) {
            float pj = __shfl_sync(0xffffffffu, p, j);
            a0 = fmaf(pj, vb[j * 64 + lane], a0);
            a1 = fmaf(pj, vb[j * 64 + lane + 32], a1);
        }
        const int b = bh >> 3, h = bh & 7;
        float* orow = g_att + (size_t)(b * Tm + iq) * Dm + (h << 6);
        orow[lane]      = a0 * inv;
        orow[lane + 32] = a1 * inv;
    }
}

// ---------------- launch -----------------------------------------------------
extern "C" void kernel_launch(void* const* d_in, const int* in_sizes, int n_in,
                              void* d_out, int out_size)
{
    const float* x  = (const float*)d_in[0];
    const float* Wq = (const float*)d_in[1];
    const float* bq = (const float*)d_in[2];
    const float* Wk = (const float*)d_in[3];
    const float* bk = (const float*)d_in[4];
    const float* Wv = (const float*)d_in[5];
    const float* bv = (const float*)d_in[6];
    const float* Wo = (const float*)d_in[7];
    const float* bo = (const float*)d_in[8];
    float* out = (float*)d_out;

    cudaFuncSetAttribute(qkv_mma_kernel,   cudaFuncAttributeMaxDynamicSharedMemorySize, 131072);
    cudaFuncSetAttribute(oproj_mma_kernel, cudaFuncAttributeMaxDynamicSharedMemorySize, 131072);
    cudaFuncSetAttribute(attn_kernel,      cudaFuncAttributeMaxDynamicSharedMemorySize, 114688);

    qkv_mma_kernel<<<dim3(Dm / 128, Mtot / 128, 3), 512, 131072>>>(x, Wq, bq, Wk, bk, Wv, bv);

    attn_kernel<<<dim3(Tm / 128, Bm * Hm), 256, 114688>>>();

    oproj_mma_kernel<<<dim3(Dm / 128, Mtot / 128), 512, 131072>>>(Wo, bo, out);
}